// round 9
// baseline (speedup 1.0000x reference)
#include <cuda_runtime.h>

#define BB 16
#define CIN 256
#define FF 76
#define NPIX (FF*FF)          /* 5776 */
#define NA 3
#define NCH 85
#define KK 50
#define PXB 128               /* pixels per block */
#define TPB 256               /* 8 warps; 4 threads per pixel-pair */
#define NPAIR (PXB/2)         /* 64 pairs per block */
#define NBLK ((NPIX + PXB - 1)/PXB)   /* 46 */
#define TOTB (NBLK*BB)                /* 736 */
#define WQ 66                 /* padded quarter stride in ull: 16B-aligned + bank-split */

typedef unsigned long long ull;

__device__ double       g_acc[5];
__device__ unsigned int g_done;

__constant__ float c_AW[9] = {1.25f,2.0f,4.125f,3.75f,7.75f,7.375f,14.5f,19.5f,46.625f};
__constant__ float c_AH[9] = {1.625f,3.75f,2.875f,7.625f,5.625f,14.875f,11.25f,24.75f,40.75f};
__constant__ float c_MW[3] = {1.25f,2.0f,4.125f};
__constant__ float c_MH[3] = {1.625f,3.75f,2.875f};

__device__ __forceinline__ float sigf(float x){ return 1.0f/(1.0f + expf(-x)); }

__device__ __forceinline__ float bce1(float p, float t){
    float pc = fminf(fmaxf(p, 1e-12f), 0.99999988f);
    return -(t*logf(pc) + (1.0f - t)*logf(1.0f - pc));
}

__device__ __forceinline__ void fma2(ull& acc, ull a, ull b){
    asm("fma.rn.f32x2 %0, %1, %2, %0;" : "+l"(acc) : "l"(a), "l"(b));
}
__device__ __forceinline__ ull add2(ull a, ull b){
    ull r; asm("add.rn.f32x2 %0, %1, %2;" : "=l"(r) : "l"(a), "l"(b)); return r;
}
__device__ __forceinline__ float2 u2f2(ull v){
    float2 r; asm("mov.b64 {%0, %1}, %2;" : "=f"(r.x), "=f"(r.y) : "l"(v)); return r;
}

__global__ void __launch_bounds__(TPB, 4)
k_main(const float* __restrict__ xin, const float* __restrict__ labels,
       const float* __restrict__ cw,  const float* __restrict__ cb,
       float* __restrict__ dout)
{
    __shared__ __align__(16) ull sW2[15][4*WQ];  /* (w,w) pairs, quarter-interleaved+pad */
    __shared__ float  sOut5[NA][PXB][5];         /* staged ch0-4: 7.7 KB */
    __shared__ float  sB[15];
    __shared__ float  sTx[KK], sTy[KK], sTw[KK], sTh[KK];
    __shared__ float  sX1[KK], sY1[KK], sX2[KK], sY2[KK], sAr[KK];
    __shared__ int    sCls[KK];
    __shared__ int    sOwn[NA*PXB];
    __shared__ int    sPos[KK];
    __shared__ int    sCnt;
    __shared__ float  sX[CIN];
    __shared__ double red[5][8];

    int tid = threadIdx.x;
    int b   = blockIdx.y;
    int n0  = blockIdx.x*PXB;
    int npb = NPIX - n0; if (npb > PXB) npb = PXB;   /* 128 or 16, even */

    for (int i = tid; i < NA*PXB; i += TPB) sOwn[i] = -1;
    if (tid == 0) sCnt = 0;

    /* weights: (w,w) pairs; quarter q of channel space at ull offset q*WQ */
    for (int i = tid; i < 15*CIN; i += TPB){
        int j = i >> 8, c = i & 255;
        int a = j/5, ch = j%5;
        float w = cw[(a*NCH + ch)*CIN + c];
        float2 p = make_float2(w, w);
        sW2[j][(c >> 6)*WQ + (c & 63)] = *reinterpret_cast<ull*>(&p);
    }
    if (tid < 15){ int a = tid/5, ch = tid%5; sB[tid] = cb[a*NCH + ch]; }
    if (tid >= 64 && tid < 64 + KK){
        int t = tid - 64;
        const float* L = labels + (b*KK + t)*5;
        float cls=L[0], xc=L[1], yc=L[2], w=L[3], h=L[4];
        bool valid = (cls + xc + yc + w + h) > 0.0f;
        float tx = xc*(float)FF, ty = yc*(float)FF;
        float tw = w *(float)FF, th = h *(float)FF;
        sTx[t]=tx; sTy[t]=ty; sTw[t]=tw; sTh[t]=th;
        sCls[t] = (int)cls;
        if (valid){
            sX1[t]=tx-tw*0.5f; sY1[t]=ty-th*0.5f;
            sX2[t]=tx+tw*0.5f; sY2[t]=ty+th*0.5f;
            sAr[t]=tw*th;
        } else {
            sX1[t]= 3.0e38f; sY1[t]= 3.0e38f;
            sX2[t]=-3.0e38f; sY2[t]=-3.0e38f;
            sAr[t]= 0.0f;
        }
        float ta = tw*th;
        float best = -1.0f; int bn = 0;
        #pragma unroll
        for (int a = 0; a < 9; a++){
            float inter = fminf(tw, c_AW[a]) * fminf(th, c_AH[a]);
            float iou = inter / (ta + c_AW[a]*c_AH[a] - inter);
            if (iou > best){ best = iou; bn = a; }
        }
        if (valid && bn < 3){
            int ii = (int)tx, jj = (int)ty;
            int slot = jj*FF + ii - n0;
            if (slot >= 0 && slot < PXB) atomicMax(&sOwn[bn*PXB + slot], t);
        }
    }
    __syncthreads();

    int lane = tid & 31;
    int wrp  = tid >> 5;            /* 0..7 */
    int q    = lane >> 3;           /* channel quarter 0..3 */
    int pg   = lane & 7;            /* pair within warp group */
    int pt   = wrp*8 + pg;          /* pair index 0..63 */
    int nbase = n0 + 2*pt;
    bool pv = (2*pt < npb);
    int nb = pv ? nbase : n0;
    double l_xy=0.0, l_wh=0.0, l_obj=0.0, l_cl=0.0, l_l2=0.0;

    /* ---- conv: 64 channels per thread (quarter q), pixel-paired f32x2 ---- */
    ull acc[15];
    #pragma unroll
    for (int j = 0; j < 15; j++) acc[j] = 0ULL;
    {
        const ull* xq = reinterpret_cast<const ull*>(xin + (size_t)b*CIN*NPIX + nb);
        const int ST = NPIX/2;
        const int g0 = q*64;        /* x channel base */
        const int ws = q*WQ;        /* weight ull base (even -> 16B aligned) */
        ull x0=xq[(size_t)(g0+0)*ST], x1=xq[(size_t)(g0+1)*ST];
        ull x2=xq[(size_t)(g0+2)*ST], x3=xq[(size_t)(g0+3)*ST];
        #pragma unroll 2
        for (int c = 0; c < 64; c += 4){
            int cp = (c + 4 < 64) ? g0 + c + 4 : g0;
            ull y0=xq[(size_t)(cp+0)*ST], y1=xq[(size_t)(cp+1)*ST];
            ull y2=xq[(size_t)(cp+2)*ST], y3=xq[(size_t)(cp+3)*ST];
            #pragma unroll
            for (int j = 0; j < 15; j++){
                ulonglong2 wA = *reinterpret_cast<const ulonglong2*>(&sW2[j][ws+c]);
                ulonglong2 wB = *reinterpret_cast<const ulonglong2*>(&sW2[j][ws+c+2]);
                fma2(acc[j], wA.x, x0); fma2(acc[j], wA.y, x1);
                fma2(acc[j], wB.x, x2); fma2(acc[j], wB.y, x3);
            }
            x0=y0; x1=y1; x2=y2; x3=y3;
        }
    }
    /* combine quarters: ((q0+q1)+(q2+q3)), all lanes get full sum */
    #pragma unroll
    for (int j = 0; j < 15; j++){
        acc[j] = add2(acc[j], __shfl_xor_sync(0xffffffffu, acc[j], 8));
        acc[j] = add2(acc[j], __shfl_xor_sync(0xffffffffu, acc[j], 16));
    }

    /* ---- lanes with q<2 finalize pixel nbase+q ---- */
    if (pv && q < 2){
        int p = q;
        int n = nbase + p;
        float a2[15];
        #pragma unroll
        for (int j = 0; j < 15; j++){
            float2 f = u2f2(acc[j]);
            a2[j] = p ? f.y : f.x;
        }

        int h = n / FF, w = n % FF;
        float s0[3], s1v[3], s4v[3], r2v[3], r3v[3];
        float bx1[3], by1[3], bx2[3], by2[3], bap[3];
        #pragma unroll
        for (int a = 0; a < NA; a++){
            float r0 = a2[a*5+0] + sB[a*5+0];
            float r1 = a2[a*5+1] + sB[a*5+1];
            float r2 = a2[a*5+2] + sB[a*5+2];
            float r3 = a2[a*5+3] + sB[a*5+3];
            float r4 = a2[a*5+4] + sB[a*5+4];
            s0[a]=sigf(r0); s1v[a]=sigf(r1); s4v[a]=sigf(r4);
            r2v[a]=r2; r3v[a]=r3;
            float px = s0[a] + (float)w, py = s1v[a] + (float)h;
            float pw = expf(r2)*c_MW[a], ph = expf(r3)*c_MH[a];
            bx1[a]=px-pw*0.5f; by1[a]=py-ph*0.5f;
            bx2[a]=px+pw*0.5f; by2[a]=py+ph*0.5f;
            bap[a]=pw*ph;
        }

        bool ig[3] = {false,false,false};
        #pragma unroll 2
        for (int k = 0; k < KK; k++){
            float lx1=sX1[k], ly1=sY1[k], lx2=sX2[k], ly2=sY2[k], ar=sAr[k];
            #pragma unroll
            for (int a = 0; a < NA; a++){
                float dx = fminf(bx2[a], lx2) - fmaxf(bx1[a], lx1);
                float dy = fminf(by2[a], ly2) - fmaxf(by1[a], ly1);
                float inter = dx*dy;
                bool en = (dx > 0.0f) & (dy > 0.0f);
                ig[a] = ig[a] | (en & (inter > 0.7f*(bap[a] + ar - inter)));
            }
        }

        int slot = n - n0;
        #pragma unroll
        for (int a = 0; a < NA; a++){
            int cell = (b*NA + a)*NPIX + n;
            int k = sOwn[a*PXB + slot];
            bool m = (k >= 0);
            float obj = m ? 1.0f : (ig[a] ? 0.0f : 1.0f);
            float o4 = s4v[a] * obj;
            float* d5 = &sOut5[a][slot][0];

            if (m){
                float tx = sTx[k], ty = sTy[k], tw = sTw[k], th = sTh[k];
                int ii = (int)tx, jj = (int)ty;
                float tfx = tx - (float)ii, tfy = ty - (float)jj;
                float lw = logf(tw / c_MW[a] + 1e-16f);
                float lh = logf(th / c_MH[a] + 1e-16f);
                float sc  = sqrtf(2.0f - tw*th/(float)NPIX);
                float sc2 = sc*sc;
                l_xy += (double)((bce1(s0[a], tfx) + bce1(s1v[a], tfy)) * sc2);
                float ow2 = r2v[a]*sc, ow3 = r3v[a]*sc;
                float tw2 = lw*sc, tw3 = lh*sc;
                float d2 = ow2 - tw2, d3 = ow3 - tw3;
                l_wh += 0.5*(double)(d2*d2 + d3*d3);
                l_obj += (double)bce1(o4, 1.0f);
                float e0 = s0[a] - tfx, e1 = s1v[a] - tfy, e4 = o4 - 1.0f;
                l_l2 += (double)(e0*e0 + e1*e1 + d2*d2 + d3*d3 + e4*e4);
                int idx = atomicAdd(&sCnt, 1);
                sPos[idx] = (cell << 7) | sCls[k];
                d5[0]=s0[a]; d5[1]=s1v[a]; d5[2]=ow2; d5[3]=ow3; d5[4]=o4;
            } else {
                l_obj += (double)bce1(o4, 0.0f);
                l_l2  += (double)(o4*o4);
                d5[0]=0.0f; d5[1]=0.0f; d5[2]=0.0f; d5[3]=0.0f; d5[4]=o4;
            }
        }
    }
    __syncthreads();

    /* ---- single-pass coalesced store of the 3 output regions ---- */
    #pragma unroll
    for (int a = 0; a < NA; a++){
        size_t e0 = 6 + ((size_t)((b*NA + a)*NPIX + n0))*NCH;
        float* base = dout + e0;
        int cnt = npb*NCH;
        int pad = (int)((4 - (e0 & 3)) & 3);
        if (pad > cnt) pad = cnt;
        if (tid < pad){
            int cell = tid/NCH, c = tid - cell*NCH;
            base[tid] = (c < 5) ? sOut5[a][cell][c] : 0.0f;
        }
        int nv = (cnt - pad) >> 2;
        float4* b4 = (float4*)(base + pad);
        for (int j = tid; j < nv; j += TPB){
            int g = pad + (j << 2);
            float4 vv;
            { int cell = g/NCH,     c = g     - cell*NCH; vv.x = (c < 5) ? sOut5[a][cell][c] : 0.0f; }
            { int cell = (g+1)/NCH, c = (g+1) - cell*NCH; vv.y = (c < 5) ? sOut5[a][cell][c] : 0.0f; }
            { int cell = (g+2)/NCH, c = (g+2) - cell*NCH; vv.z = (c < 5) ? sOut5[a][cell][c] : 0.0f; }
            { int cell = (g+3)/NCH, c = (g+3) - cell*NCH; vv.w = (c < 5) ? sOut5[a][cell][c] : 0.0f; }
            b4[j] = vv;
        }
        int rem0 = pad + (nv << 2);
        if (rem0 + tid < cnt){
            int g = rem0 + tid;
            int cell = g/NCH, c = g - cell*NCH;
            base[g] = (c < 5) ? sOut5[a][cell][c] : 0.0f;
        }
    }
    __syncthreads();

    /* ---- class pass: 8 warps x 10 classes per positive ---- */
    {
        int cnt = sCnt;
        for (int qd = 0; qd < cnt; qd++){
            int pk   = sPos[qd];
            int cell = pk >> 7;
            int cls  = pk & 127;
            int a    = (cell / NPIX) % NA;
            int pix  = cell % NPIX;
            sX[tid] = xin[((size_t)b*CIN + tid)*NPIX + pix];
            __syncthreads();

            const float* wbase = cw + (size_t)(a*NCH + 5 + wrp*10)*CIN;
            float s[10];
            #pragma unroll
            for (int i = 0; i < 10; i++) s[i] = 0.0f;
            #pragma unroll
            for (int j = 0; j < 8; j++){
                float x = sX[lane + 32*j];
                #pragma unroll
                for (int i = 0; i < 10; i++)
                    s[i] += wbase[(size_t)i*CIN + lane + 32*j] * x;
            }
            #pragma unroll
            for (int i = 0; i < 10; i++){
                #pragma unroll
                for (int off = 16; off; off >>= 1)
                    s[i] += __shfl_down_sync(0xffffffffu, s[i], off);
            }
            if (lane == 0){
                float* oc = dout + 6 + (size_t)cell*NCH;
                #pragma unroll
                for (int i = 0; i < 10; i++){
                    int c = wrp*10 + i;
                    float raw = s[i] + cb[a*NCH + 5 + c];
                    float sg = sigf(raw);
                    float t = (c == cls) ? 1.0f : 0.0f;
                    l_cl += (double)bce1(sg, t);
                    float d = sg - t;
                    l_l2 += (double)(d*d);
                    oc[5 + c] = sg;
                }
            }
            __syncthreads();
        }
    }

    /* ---- block reduce 5 doubles -> atomicAdd ---- */
    #pragma unroll
    for (int off = 16; off; off >>= 1){
        l_xy  += __shfl_down_sync(0xffffffffu, l_xy,  off);
        l_wh  += __shfl_down_sync(0xffffffffu, l_wh,  off);
        l_obj += __shfl_down_sync(0xffffffffu, l_obj, off);
        l_cl  += __shfl_down_sync(0xffffffffu, l_cl,  off);
        l_l2  += __shfl_down_sync(0xffffffffu, l_l2,  off);
    }
    if (lane == 0){ red[0][wrp]=l_xy; red[1][wrp]=l_wh; red[2][wrp]=l_obj; red[3][wrp]=l_cl; red[4][wrp]=l_l2; }
    __syncthreads();
    if (tid == 0){
        double a0=0,a1=0,a2=0,a3=0,a4=0;
        #pragma unroll
        for (int i = 0; i < 8; i++){ a0+=red[0][i]; a1+=red[1][i]; a2+=red[2][i]; a3+=red[3][i]; a4+=red[4][i]; }
        atomicAdd(&g_acc[0], a0);
        atomicAdd(&g_acc[1], a1);
        atomicAdd(&g_acc[2], a2);
        atomicAdd(&g_acc[3], a3);
        atomicAdd(&g_acc[4], a4);

        __threadfence();
        unsigned int t = atomicInc(&g_done, TOTB - 1);
        if (t == TOTB - 1){
            double xy = atomicAdd(&g_acc[0], 0.0);
            double wh = atomicAdd(&g_acc[1], 0.0);
            double ob = atomicAdd(&g_acc[2], 0.0);
            double cl = atomicAdd(&g_acc[3], 0.0);
            double l2 = atomicAdd(&g_acc[4], 0.0);
            dout[0] = (float)(xy + wh + ob + cl);
            dout[1] = (float)xy;
            dout[2] = (float)wh;
            dout[3] = (float)ob;
            dout[4] = (float)cl;
            dout[5] = (float)l2;
            g_acc[0]=0.0; g_acc[1]=0.0; g_acc[2]=0.0; g_acc[3]=0.0; g_acc[4]=0.0;
            __threadfence();
        }
    }
}

extern "C" void kernel_launch(void* const* d_in, const int* in_sizes, int n_in,
                              void* d_out, int out_size)
{
    const float* xin    = (const float*)d_in[0];
    const float* labels = (const float*)d_in[1];
    const float* cw     = (const float*)d_in[2];
    const float* cb     = (const float*)d_in[3];
    float* dout = (float*)d_out;

    dim3 g(NBLK, BB);   /* 46 x 16 = 736 blocks, 256 threads */
    k_main<<<g, TPB>>>(xin, labels, cw, cb, dout);
}

// round 10
// speedup vs baseline: 1.2263x; 1.2263x over previous
#include <cuda_runtime.h>

#define BB 16
#define CIN 256
#define FF 76
#define NPIX (FF*FF)          /* 5776 */
#define NA 3
#define NCH 85
#define KK 50
#define PXB 128               /* pixels per block */
#define TPB 128
#define NPAIR (PXB/2)         /* 64 pixel-pairs per block */
#define NBLK ((NPIX + PXB - 1)/PXB)   /* 46 */
#define TOTB (NBLK*BB)                /* 736 */

typedef unsigned long long ull;

__device__ double       g_acc[5];
__device__ unsigned int g_done;

__constant__ float c_AW[9] = {1.25f,2.0f,4.125f,3.75f,7.75f,7.375f,14.5f,19.5f,46.625f};
__constant__ float c_AH[9] = {1.625f,3.75f,2.875f,7.625f,5.625f,14.875f,11.25f,24.75f,40.75f};
__constant__ float c_MW[3] = {1.25f,2.0f,4.125f};
__constant__ float c_MH[3] = {1.625f,3.75f,2.875f};

__device__ __forceinline__ float sigf(float x){ return 1.0f/(1.0f + expf(-x)); }

__device__ __forceinline__ float bce1(float p, float t){
    float pc = fminf(fmaxf(p, 1e-12f), 0.99999988f);
    return -(t*logf(pc) + (1.0f - t)*logf(1.0f - pc));
}

__device__ __forceinline__ void fma2(ull& acc, ull a, ull b){
    asm("fma.rn.f32x2 %0, %1, %2, %0;" : "+l"(acc) : "l"(a), "l"(b));
}
__device__ __forceinline__ float2 u2f2(ull v){
    float2 r; asm("mov.b64 {%0, %1}, %2;" : "=f"(r.x), "=f"(r.y) : "l"(v)); return r;
}

__global__ void __launch_bounds__(TPB, 5)
k_main(const float* __restrict__ xin, const float* __restrict__ labels,
       const float* __restrict__ cw,  const float* __restrict__ cb,
       float* __restrict__ dout)
{
    __shared__ __align__(16) ull sW2[15][CIN];   /* (w,w) pairs: 30.7 KB */
    __shared__ union {
        ull   part[2][15][NPAIR];        /* conv partials per half (phase A) */
        float out5[NA][PXB][5];          /* staged ch0-4 values    (phase B) */
    } sU;
    __shared__ float  sB[15];
    __shared__ float  sTx[KK], sTy[KK], sTw[KK], sTh[KK];
    __shared__ float  sX1[KK], sY1[KK], sX2[KK], sY2[KK], sAr[KK];
    __shared__ int    sCls[KK];
    __shared__ int    sOwn[NA*PXB];
    __shared__ int    sPos[KK];
    __shared__ int    sCnt;
    __shared__ float  sX[CIN];
    __shared__ double red[5][4];

    int tid = threadIdx.x;
    int b   = blockIdx.y;
    int n0  = blockIdx.x*PXB;
    int npb = NPIX - n0; if (npb > PXB) npb = PXB;   /* 128 or 16, even */

    for (int i = tid; i < NA*PXB; i += TPB) sOwn[i] = -1;
    if (tid == 0) sCnt = 0;

    /* weights as (w,w) pairs */
    for (int i = tid; i < 15*CIN; i += TPB){
        int j = i >> 8, c = i & 255;
        int a = j/5, ch = j%5;
        float w = cw[(a*NCH + ch)*CIN + c];
        float2 p = make_float2(w, w);
        sW2[j][c] = *reinterpret_cast<ull*>(&p);
    }
    if (tid < 15){ int a = tid/5, ch = tid%5; sB[tid] = cb[a*NCH + ch]; }
    if (tid >= 64 && tid < 64 + KK){
        int t = tid - 64;
        const float* L = labels + (b*KK + t)*5;
        float cls=L[0], xc=L[1], yc=L[2], w=L[3], h=L[4];
        bool valid = (cls + xc + yc + w + h) > 0.0f;
        float tx = xc*(float)FF, ty = yc*(float)FF;
        float tw = w *(float)FF, th = h *(float)FF;
        sTx[t]=tx; sTy[t]=ty; sTw[t]=tw; sTh[t]=th;
        sCls[t] = (int)cls;
        if (valid){
            sX1[t]=tx-tw*0.5f; sY1[t]=ty-th*0.5f;
            sX2[t]=tx+tw*0.5f; sY2[t]=ty+th*0.5f;
            sAr[t]=tw*th;
        } else {
            sX1[t]= 3.0e38f; sY1[t]= 3.0e38f;
            sX2[t]=-3.0e38f; sY2[t]=-3.0e38f;
            sAr[t]= 0.0f;
        }
        float ta = tw*th;
        float best = -1.0f; int bn = 0;
        #pragma unroll
        for (int a = 0; a < 9; a++){
            float inter = fminf(tw, c_AW[a]) * fminf(th, c_AH[a]);
            float iou = inter / (ta + c_AW[a]*c_AH[a] - inter);
            if (iou > best){ best = iou; bn = a; }
        }
        if (valid && bn < 3){
            int ii = (int)tx, jj = (int)ty;
            int slot = jj*FF + ii - n0;
            if (slot >= 0 && slot < PXB) atomicMax(&sOwn[bn*PXB + slot], t);
        }
    }
    __syncthreads();

    int pt   = tid & (NPAIR-1);
    int half = tid >> 6;
    int nbase = n0 + 2*pt;
    bool pv = (2*pt < npb);
    int nb = pv ? nbase : n0;
    double l_xy=0.0, l_wh=0.0, l_obj=0.0, l_cl=0.0, l_l2=0.0;

    /* ---- 15-ch conv, pixel-paired f32x2, channels split across halves ----
       pointer-increment prefetch, last step peeled (no per-step selects)  */
    ull acc[15];
    #pragma unroll
    for (int j = 0; j < 15; j++) acc[j] = 0ULL;
    {
        const int ST = NPIX/2;
        const ull* xp = reinterpret_cast<const ull*>(xin + (size_t)b*CIN*NPIX + nb)
                        + (size_t)(half*128)*ST;
        ull x0=xp[0], x1=xp[ST], x2=xp[2*ST], x3=xp[3*ST];
        #pragma unroll 2
        for (int c = 0; c < 124; c += 4){
            const ull* xn = xp + (size_t)4*ST;
            ull y0=xn[0], y1=xn[ST], y2=xn[2*ST], y3=xn[3*ST];
            int cc = half*128 + c;
            #pragma unroll
            for (int j = 0; j < 15; j++){
                ulonglong2 wA = *reinterpret_cast<const ulonglong2*>(&sW2[j][cc]);
                ulonglong2 wB = *reinterpret_cast<const ulonglong2*>(&sW2[j][cc+2]);
                fma2(acc[j], wA.x, x0); fma2(acc[j], wA.y, x1);
                fma2(acc[j], wB.x, x2); fma2(acc[j], wB.y, x3);
            }
            x0=y0; x1=y1; x2=y2; x3=y3;
            xp = xn;
        }
        /* peeled last step: c = 124 */
        int cc = half*128 + 124;
        #pragma unroll
        for (int j = 0; j < 15; j++){
            ulonglong2 wA = *reinterpret_cast<const ulonglong2*>(&sW2[j][cc]);
            ulonglong2 wB = *reinterpret_cast<const ulonglong2*>(&sW2[j][cc+2]);
            fma2(acc[j], wA.x, x0); fma2(acc[j], wA.y, x1);
            fma2(acc[j], wB.x, x2); fma2(acc[j], wB.y, x3);
        }
    }
    #pragma unroll
    for (int j = 0; j < 15; j++) sU.part[half][j][pt] = acc[j];
    __syncthreads();

    /* ---- each thread finalizes ONE pixel: n = nbase + half ---- */
    float o5[3][5];

    if (pv){
        int p = half;
        int n = nbase + p;
        float a2[15];
        #pragma unroll
        for (int j = 0; j < 15; j++){
            float2 f0 = u2f2(sU.part[0][j][pt]);
            float2 f1 = u2f2(sU.part[1][j][pt]);
            a2[j] = p ? (f0.y + f1.y) : (f0.x + f1.x);
        }

        int h = n / FF, w = n % FF;
        float s0[3], s1v[3], s4v[3], r2v[3], r3v[3];
        float bx1[3], by1[3], bx2[3], by2[3], bap[3];
        #pragma unroll
        for (int a = 0; a < NA; a++){
            float r0 = a2[a*5+0] + sB[a*5+0];
            float r1 = a2[a*5+1] + sB[a*5+1];
            float r2 = a2[a*5+2] + sB[a*5+2];
            float r3 = a2[a*5+3] + sB[a*5+3];
            float r4 = a2[a*5+4] + sB[a*5+4];
            s0[a]=sigf(r0); s1v[a]=sigf(r1); s4v[a]=sigf(r4);
            r2v[a]=r2; r3v[a]=r3;
            float px = s0[a] + (float)w, py = s1v[a] + (float)h;
            float pw = expf(r2)*c_MW[a], ph = expf(r3)*c_MH[a];
            bx1[a]=px-pw*0.5f; by1[a]=py-ph*0.5f;
            bx2[a]=px+pw*0.5f; by2[a]=py+ph*0.5f;
            bap[a]=pw*ph;
        }

        bool ig[3] = {false,false,false};
        #pragma unroll 2
        for (int k = 0; k < KK; k++){
            float lx1=sX1[k], ly1=sY1[k], lx2=sX2[k], ly2=sY2[k], ar=sAr[k];
            #pragma unroll
            for (int a = 0; a < NA; a++){
                float dx = fminf(bx2[a], lx2) - fmaxf(bx1[a], lx1);
                float dy = fminf(by2[a], ly2) - fmaxf(by1[a], ly1);
                float inter = dx*dy;
                bool en = (dx > 0.0f) & (dy > 0.0f);
                ig[a] = ig[a] | (en & (inter > 0.7f*(bap[a] + ar - inter)));
            }
        }

        #pragma unroll
        for (int a = 0; a < NA; a++){
            int cell = (b*NA + a)*NPIX + n;
            int k = sOwn[a*PXB + (n - n0)];
            bool m = (k >= 0);
            float obj = m ? 1.0f : (ig[a] ? 0.0f : 1.0f);
            float o4 = s4v[a] * obj;

            if (m){
                float tx = sTx[k], ty = sTy[k], tw = sTw[k], th = sTh[k];
                int ii = (int)tx, jj = (int)ty;
                float tfx = tx - (float)ii, tfy = ty - (float)jj;
                float lw = logf(tw / c_MW[a] + 1e-16f);
                float lh = logf(th / c_MH[a] + 1e-16f);
                float sc  = sqrtf(2.0f - tw*th/(float)NPIX);
                float sc2 = sc*sc;
                l_xy += (double)((bce1(s0[a], tfx) + bce1(s1v[a], tfy)) * sc2);
                float ow2 = r2v[a]*sc, ow3 = r3v[a]*sc;
                float tw2 = lw*sc, tw3 = lh*sc;
                float d2 = ow2 - tw2, d3 = ow3 - tw3;
                l_wh += 0.5*(double)(d2*d2 + d3*d3);
                l_obj += (double)bce1(o4, 1.0f);
                float e0 = s0[a] - tfx, e1 = s1v[a] - tfy, e4 = o4 - 1.0f;
                l_l2 += (double)(e0*e0 + e1*e1 + d2*d2 + d3*d3 + e4*e4);
                int idx = atomicAdd(&sCnt, 1);
                sPos[idx] = (cell << 7) | sCls[k];
                o5[a][0]=s0[a]; o5[a][1]=s1v[a]; o5[a][2]=ow2; o5[a][3]=ow3; o5[a][4]=o4;
            } else {
                l_obj += (double)bce1(o4, 0.0f);
                l_l2  += (double)(o4*o4);
                o5[a][0]=0.0f; o5[a][1]=0.0f; o5[a][2]=0.0f; o5[a][3]=0.0f; o5[a][4]=o4;
            }
        }
    }
    __syncthreads();   /* all sU.part reads done -> union repurpose safe */

    if (pv){
        int slot = nbase + half - n0;
        #pragma unroll
        for (int a = 0; a < NA; a++){
            float* d5 = &sU.out5[a][slot][0];
            d5[0]=o5[a][0]; d5[1]=o5[a][1]; d5[2]=o5[a][2];
            d5[3]=o5[a][3]; d5[4]=o5[a][4];
        }
    }
    __syncthreads();

    /* ---- single-pass coalesced store, incremental (cell,c) indexing ---- */
    #pragma unroll
    for (int a = 0; a < NA; a++){
        size_t e0 = 6 + ((size_t)((b*NA + a)*NPIX + n0))*NCH;
        float* base = dout + e0;
        int cnt = npb*NCH;
        int pad = (int)((4 - (e0 & 3)) & 3);
        if (pad > cnt) pad = cnt;
        if (tid < pad){
            int cell = tid/NCH, c = tid - cell*NCH;
            base[tid] = (c < 5) ? sU.out5[a][cell][c] : 0.0f;
        }
        int nv = (cnt - pad) >> 2;
        float4* b4 = (float4*)(base + pad);
        if (tid < nv){
            int g = pad + (tid << 2);
            int cell = g/NCH;
            int c = g - cell*NCH;
            for (int j = tid; j < nv; j += TPB){
                float4 vv;
                int c0=c,   cl0=cell;
                vv.x = (c0 < 5) ? sU.out5[a][cl0][c0] : 0.0f;
                int c1=c0+1, cl1=cl0; if (c1 == NCH){ c1 = 0; cl1++; }
                vv.y = (c1 < 5) ? sU.out5[a][cl1][c1] : 0.0f;
                int c2=c1+1, cl2=cl1; if (c2 == NCH){ c2 = 0; cl2++; }
                vv.z = (c2 < 5) ? sU.out5[a][cl2][c2] : 0.0f;
                int c3=c2+1, cl3=cl2; if (c3 == NCH){ c3 = 0; cl3++; }
                vv.w = (c3 < 5) ? sU.out5[a][cl3][c3] : 0.0f;
                b4[j] = vv;
                /* advance TPB*4 = 512 = 6*85 + 2 elements */
                c += 2; cell += 6;
                if (c >= NCH){ c -= NCH; cell++; }
            }
        }
        int rem0 = pad + (nv << 2);
        if (rem0 + tid < cnt){
            int g = rem0 + tid;
            int cell = g/NCH, c = g - cell*NCH;
            base[g] = (c < 5) ? sU.out5[a][cell][c] : 0.0f;
        }
    }
    __syncthreads();

    /* ---- class pass for positives owned by this block ---- */
    {
        int lane = tid & 31, wid = tid >> 5;
        int cnt = sCnt;
        for (int q = 0; q < cnt; q++){
            int pk   = sPos[q];
            int cell = pk >> 7;
            int cls  = pk & 127;
            int a    = (cell / NPIX) % NA;
            int pix  = cell % NPIX;
            sX[tid]       = xin[((size_t)b*CIN + tid)*NPIX + pix];
            sX[tid + 128] = xin[((size_t)b*CIN + tid + 128)*NPIX + pix];
            __syncthreads();

            const float* wbase = cw + (size_t)(a*NCH + 5 + wid*20)*CIN;
            float s[20];
            #pragma unroll
            for (int i = 0; i < 20; i++) s[i] = 0.0f;
            #pragma unroll
            for (int j = 0; j < 8; j++){
                float x = sX[lane + 32*j];
                #pragma unroll
                for (int i = 0; i < 20; i++)
                    s[i] += wbase[(size_t)i*CIN + lane + 32*j] * x;
            }
            #pragma unroll
            for (int i = 0; i < 20; i++){
                #pragma unroll
                for (int off = 16; off; off >>= 1)
                    s[i] += __shfl_down_sync(0xffffffffu, s[i], off);
            }
            if (lane == 0){
                float* oc = dout + 6 + (size_t)cell*NCH;
                #pragma unroll
                for (int i = 0; i < 20; i++){
                    int c = wid*20 + i;
                    float raw = s[i] + cb[a*NCH + 5 + c];
                    float sg = sigf(raw);
                    float t = (c == cls) ? 1.0f : 0.0f;
                    l_cl += (double)bce1(sg, t);
                    float d = sg - t;
                    l_l2 += (double)(d*d);
                    oc[5 + c] = sg;
                }
            }
            __syncthreads();
        }
    }

    /* ---- block reduce 5 doubles -> atomicAdd ---- */
    int lane = tid & 31, wid = tid >> 5;
    #pragma unroll
    for (int off = 16; off; off >>= 1){
        l_xy  += __shfl_down_sync(0xffffffffu, l_xy,  off);
        l_wh  += __shfl_down_sync(0xffffffffu, l_wh,  off);
        l_obj += __shfl_down_sync(0xffffffffu, l_obj, off);
        l_cl  += __shfl_down_sync(0xffffffffu, l_cl,  off);
        l_l2  += __shfl_down_sync(0xffffffffu, l_l2,  off);
    }
    if (lane == 0){ red[0][wid]=l_xy; red[1][wid]=l_wh; red[2][wid]=l_obj; red[3][wid]=l_cl; red[4][wid]=l_l2; }
    __syncthreads();
    if (tid == 0){
        double a0=0,a1=0,a2=0,a3=0,a4=0;
        #pragma unroll
        for (int i = 0; i < 4; i++){ a0+=red[0][i]; a1+=red[1][i]; a2+=red[2][i]; a3+=red[3][i]; a4+=red[4][i]; }
        atomicAdd(&g_acc[0], a0);
        atomicAdd(&g_acc[1], a1);
        atomicAdd(&g_acc[2], a2);
        atomicAdd(&g_acc[3], a3);
        atomicAdd(&g_acc[4], a4);

        __threadfence();
        unsigned int t = atomicInc(&g_done, TOTB - 1);
        if (t == TOTB - 1){
            double xy = atomicAdd(&g_acc[0], 0.0);
            double wh = atomicAdd(&g_acc[1], 0.0);
            double ob = atomicAdd(&g_acc[2], 0.0);
            double cl = atomicAdd(&g_acc[3], 0.0);
            double l2 = atomicAdd(&g_acc[4], 0.0);
            dout[0] = (float)(xy + wh + ob + cl);
            dout[1] = (float)xy;
            dout[2] = (float)wh;
            dout[3] = (float)ob;
            dout[4] = (float)cl;
            dout[5] = (float)l2;
            g_acc[0]=0.0; g_acc[1]=0.0; g_acc[2]=0.0; g_acc[3]=0.0; g_acc[4]=0.0;
            __threadfence();
        }
    }
}

extern "C" void kernel_launch(void* const* d_in, const int* in_sizes, int n_in,
                              void* d_out, int out_size)
{
    const float* xin    = (const float*)d_in[0];
    const float* labels = (const float*)d_in[1];
    const float* cw     = (const float*)d_in[2];
    const float* cb     = (const float*)d_in[3];
    float* dout = (float*)d_out;

    dim3 g(NBLK, BB);   /* 46 x 16 = 736 blocks */
    k_main<<<g, TPB>>>(xin, labels, cw, cb, dout);
}

// round 11
// speedup vs baseline: 1.2273x; 1.0008x over previous
#include <cuda_runtime.h>

#define BB 16
#define CIN 256
#define FF 76
#define NPIX (FF*FF)          /* 5776 */
#define NA 3
#define NCH 85
#define KK 50
#define PXB 128               /* pixels per block */
#define TPB 128
#define NPAIR (PXB/2)         /* 64 pixel-pairs per block */
#define NBLK ((NPIX + PXB - 1)/PXB)   /* 46 */
#define TOTB (NBLK*BB)                /* 736 */

typedef unsigned long long ull;

__device__ double       g_acc[5];
__device__ unsigned int g_done;

__constant__ float c_AW[9] = {1.25f,2.0f,4.125f,3.75f,7.75f,7.375f,14.5f,19.5f,46.625f};
__constant__ float c_AH[9] = {1.625f,3.75f,2.875f,7.625f,5.625f,14.875f,11.25f,24.75f,40.75f};
__constant__ float c_MW[3] = {1.25f,2.0f,4.125f};
__constant__ float c_MH[3] = {1.625f,3.75f,2.875f};

__device__ __forceinline__ float sigf(float x){ return 1.0f/(1.0f + expf(-x)); }

__device__ __forceinline__ float bce1(float p, float t){
    float pc = fminf(fmaxf(p, 1e-12f), 0.99999988f);
    return -(t*logf(pc) + (1.0f - t)*logf(1.0f - pc));
}

__device__ __forceinline__ void fma2(ull& acc, ull a, ull b){
    asm("fma.rn.f32x2 %0, %1, %2, %0;" : "+l"(acc) : "l"(a), "l"(b));
}
__device__ __forceinline__ float2 u2f2(ull v){
    float2 r; asm("mov.b64 {%0, %1}, %2;" : "=f"(r.x), "=f"(r.y) : "l"(v)); return r;
}

__global__ void __launch_bounds__(TPB, 4)
k_main(const float* __restrict__ xin, const float* __restrict__ labels,
       const float* __restrict__ cw,  const float* __restrict__ cb,
       float* __restrict__ dout)
{
    __shared__ __align__(16) ull sW2[15][CIN];   /* (w,w) pairs: 30.7 KB */
    __shared__ union {
        ull   part[2][15][NPAIR];        /* conv partials per half (phase A) */
        float out5[NA][PXB][5];          /* staged ch0-4 values    (phase B) */
    } sU;
    __shared__ float  sB[15];
    __shared__ float  sTx[KK], sTy[KK], sTw[KK], sTh[KK];
    __shared__ float  sX1[KK], sY1[KK], sX2[KK], sY2[KK], sAr[KK];
    __shared__ int    sCls[KK];
    __shared__ int    sOwn[NA*PXB];
    __shared__ int    sPos[KK];
    __shared__ int    sCnt;
    __shared__ float  sX[CIN];
    __shared__ double red[5][4];

    int tid = threadIdx.x;
    int b   = blockIdx.y;
    int n0  = blockIdx.x*PXB;
    int npb = NPIX - n0; if (npb > PXB) npb = PXB;   /* 128 or 16, even */

    for (int i = tid; i < NA*PXB; i += TPB) sOwn[i] = -1;
    if (tid == 0) sCnt = 0;

    /* weights as (w,w) pairs */
    for (int i = tid; i < 15*CIN; i += TPB){
        int j = i >> 8, c = i & 255;
        int a = j/5, ch = j%5;
        float w = cw[(a*NCH + ch)*CIN + c];
        float2 p = make_float2(w, w);
        sW2[j][c] = *reinterpret_cast<ull*>(&p);
    }
    if (tid < 15){ int a = tid/5, ch = tid%5; sB[tid] = cb[a*NCH + ch]; }
    if (tid >= 64 && tid < 64 + KK){
        int t = tid - 64;
        const float* L = labels + (b*KK + t)*5;
        float cls=L[0], xc=L[1], yc=L[2], w=L[3], h=L[4];
        bool valid = (cls + xc + yc + w + h) > 0.0f;
        float tx = xc*(float)FF, ty = yc*(float)FF;
        float tw = w *(float)FF, th = h *(float)FF;
        sTx[t]=tx; sTy[t]=ty; sTw[t]=tw; sTh[t]=th;
        sCls[t] = (int)cls;
        if (valid){
            sX1[t]=tx-tw*0.5f; sY1[t]=ty-th*0.5f;
            sX2[t]=tx+tw*0.5f; sY2[t]=ty+th*0.5f;
            sAr[t]=tw*th;
        } else {
            sX1[t]= 3.0e38f; sY1[t]= 3.0e38f;
            sX2[t]=-3.0e38f; sY2[t]=-3.0e38f;
            sAr[t]= 0.0f;
        }
        float ta = tw*th;
        float best = -1.0f; int bn = 0;
        #pragma unroll
        for (int a = 0; a < 9; a++){
            float inter = fminf(tw, c_AW[a]) * fminf(th, c_AH[a]);
            float iou = inter / (ta + c_AW[a]*c_AH[a] - inter);
            if (iou > best){ best = iou; bn = a; }
        }
        if (valid && bn < 3){
            int ii = (int)tx, jj = (int)ty;
            int slot = jj*FF + ii - n0;
            if (slot >= 0 && slot < PXB) atomicMax(&sOwn[bn*PXB + slot], t);
        }
    }
    __syncthreads();

    int pt   = tid & (NPAIR-1);
    int half = tid >> 6;
    int nbase = n0 + 2*pt;
    bool pv = (2*pt < npb);
    int nb = pv ? nbase : n0;
    double l_xy=0.0, l_wh=0.0, l_obj=0.0, l_cl=0.0, l_l2=0.0;

    /* ---- 15-ch conv, pixel-paired f32x2, channels split across halves ----
       depth-16 software pipeline: two groups of 8 in flight               */
    ull acc[15];
    #pragma unroll
    for (int j = 0; j < 15; j++) acc[j] = 0ULL;
    {
        const ull* xq = reinterpret_cast<const ull*>(xin + (size_t)b*CIN*NPIX + nb);
        const int ST = NPIX/2;
        const int c0 = half*128;
        ull xa0=xq[(size_t)(c0+ 0)*ST], xa1=xq[(size_t)(c0+ 1)*ST];
        ull xa2=xq[(size_t)(c0+ 2)*ST], xa3=xq[(size_t)(c0+ 3)*ST];
        ull xa4=xq[(size_t)(c0+ 4)*ST], xa5=xq[(size_t)(c0+ 5)*ST];
        ull xa6=xq[(size_t)(c0+ 6)*ST], xa7=xq[(size_t)(c0+ 7)*ST];
        ull xb0=xq[(size_t)(c0+ 8)*ST], xb1=xq[(size_t)(c0+ 9)*ST];
        ull xb2=xq[(size_t)(c0+10)*ST], xb3=xq[(size_t)(c0+11)*ST];
        ull xb4=xq[(size_t)(c0+12)*ST], xb5=xq[(size_t)(c0+13)*ST];
        ull xb6=xq[(size_t)(c0+14)*ST], xb7=xq[(size_t)(c0+15)*ST];
        #pragma unroll 1
        for (int c = 0; c < 128; c += 16){
            int cp = (c + 16 < 128) ? c0 + c + 16 : c0;
            ull y0=xq[(size_t)(cp+0)*ST], y1=xq[(size_t)(cp+1)*ST];
            ull y2=xq[(size_t)(cp+2)*ST], y3=xq[(size_t)(cp+3)*ST];
            ull y4=xq[(size_t)(cp+4)*ST], y5=xq[(size_t)(cp+5)*ST];
            ull y6=xq[(size_t)(cp+6)*ST], y7=xq[(size_t)(cp+7)*ST];
            int cc = c0 + c;
            #pragma unroll
            for (int j = 0; j < 15; j++){
                ulonglong2 wA = *reinterpret_cast<const ulonglong2*>(&sW2[j][cc]);
                ulonglong2 wB = *reinterpret_cast<const ulonglong2*>(&sW2[j][cc+2]);
                ulonglong2 wC = *reinterpret_cast<const ulonglong2*>(&sW2[j][cc+4]);
                ulonglong2 wD = *reinterpret_cast<const ulonglong2*>(&sW2[j][cc+6]);
                fma2(acc[j], wA.x, xa0); fma2(acc[j], wA.y, xa1);
                fma2(acc[j], wB.x, xa2); fma2(acc[j], wB.y, xa3);
                fma2(acc[j], wC.x, xa4); fma2(acc[j], wC.y, xa5);
                fma2(acc[j], wD.x, xa6); fma2(acc[j], wD.y, xa7);
            }
            int cq = (c + 24 < 128) ? c0 + c + 24 : c0;
            ull z0=xq[(size_t)(cq+0)*ST], z1=xq[(size_t)(cq+1)*ST];
            ull z2=xq[(size_t)(cq+2)*ST], z3=xq[(size_t)(cq+3)*ST];
            ull z4=xq[(size_t)(cq+4)*ST], z5=xq[(size_t)(cq+5)*ST];
            ull z6=xq[(size_t)(cq+6)*ST], z7=xq[(size_t)(cq+7)*ST];
            int cd = c0 + c + 8;
            #pragma unroll
            for (int j = 0; j < 15; j++){
                ulonglong2 wA = *reinterpret_cast<const ulonglong2*>(&sW2[j][cd]);
                ulonglong2 wB = *reinterpret_cast<const ulonglong2*>(&sW2[j][cd+2]);
                ulonglong2 wC = *reinterpret_cast<const ulonglong2*>(&sW2[j][cd+4]);
                ulonglong2 wD = *reinterpret_cast<const ulonglong2*>(&sW2[j][cd+6]);
                fma2(acc[j], wA.x, xb0); fma2(acc[j], wA.y, xb1);
                fma2(acc[j], wB.x, xb2); fma2(acc[j], wB.y, xb3);
                fma2(acc[j], wC.x, xb4); fma2(acc[j], wC.y, xb5);
                fma2(acc[j], wD.x, xb6); fma2(acc[j], wD.y, xb7);
            }
            xa0=y0; xa1=y1; xa2=y2; xa3=y3; xa4=y4; xa5=y5; xa6=y6; xa7=y7;
            xb0=z0; xb1=z1; xb2=z2; xb3=z3; xb4=z4; xb5=z5; xb6=z6; xb7=z7;
        }
    }
    #pragma unroll
    for (int j = 0; j < 15; j++) sU.part[half][j][pt] = acc[j];
    __syncthreads();

    /* ---- each thread finalizes ONE pixel: n = nbase + half ---- */
    float o5[3][5];

    if (pv){
        int p = half;
        int n = nbase + p;
        float a2[15];
        #pragma unroll
        for (int j = 0; j < 15; j++){
            float2 f0 = u2f2(sU.part[0][j][pt]);
            float2 f1 = u2f2(sU.part[1][j][pt]);
            a2[j] = p ? (f0.y + f1.y) : (f0.x + f1.x);
        }

        int h = n / FF, w = n % FF;
        float s0[3], s1v[3], s4v[3], r2v[3], r3v[3];
        float bx1[3], by1[3], bx2[3], by2[3], bap[3];
        #pragma unroll
        for (int a = 0; a < NA; a++){
            float r0 = a2[a*5+0] + sB[a*5+0];
            float r1 = a2[a*5+1] + sB[a*5+1];
            float r2 = a2[a*5+2] + sB[a*5+2];
            float r3 = a2[a*5+3] + sB[a*5+3];
            float r4 = a2[a*5+4] + sB[a*5+4];
            s0[a]=sigf(r0); s1v[a]=sigf(r1); s4v[a]=sigf(r4);
            r2v[a]=r2; r3v[a]=r3;
            float px = s0[a] + (float)w, py = s1v[a] + (float)h;
            float pw = expf(r2)*c_MW[a], ph = expf(r3)*c_MH[a];
            bx1[a]=px-pw*0.5f; by1[a]=py-ph*0.5f;
            bx2[a]=px+pw*0.5f; by2[a]=py+ph*0.5f;
            bap[a]=pw*ph;
        }

        bool ig[3] = {false,false,false};
        #pragma unroll 2
        for (int k = 0; k < KK; k++){
            float lx1=sX1[k], ly1=sY1[k], lx2=sX2[k], ly2=sY2[k], ar=sAr[k];
            #pragma unroll
            for (int a = 0; a < NA; a++){
                float dx = fminf(bx2[a], lx2) - fmaxf(bx1[a], lx1);
                float dy = fminf(by2[a], ly2) - fmaxf(by1[a], ly1);
                float inter = dx*dy;
                bool en = (dx > 0.0f) & (dy > 0.0f);
                ig[a] = ig[a] | (en & (inter > 0.7f*(bap[a] + ar - inter)));
            }
        }

        #pragma unroll
        for (int a = 0; a < NA; a++){
            int cell = (b*NA + a)*NPIX + n;
            int k = sOwn[a*PXB + (n - n0)];
            bool m = (k >= 0);
            float obj = m ? 1.0f : (ig[a] ? 0.0f : 1.0f);
            float o4 = s4v[a] * obj;

            if (m){
                float tx = sTx[k], ty = sTy[k], tw = sTw[k], th = sTh[k];
                int ii = (int)tx, jj = (int)ty;
                float tfx = tx - (float)ii, tfy = ty - (float)jj;
                float lw = logf(tw / c_MW[a] + 1e-16f);
                float lh = logf(th / c_MH[a] + 1e-16f);
                float sc  = sqrtf(2.0f - tw*th/(float)NPIX);
                float sc2 = sc*sc;
                l_xy += (double)((bce1(s0[a], tfx) + bce1(s1v[a], tfy)) * sc2);
                float ow2 = r2v[a]*sc, ow3 = r3v[a]*sc;
                float tw2 = lw*sc, tw3 = lh*sc;
                float d2 = ow2 - tw2, d3 = ow3 - tw3;
                l_wh += 0.5*(double)(d2*d2 + d3*d3);
                l_obj += (double)bce1(o4, 1.0f);
                float e0 = s0[a] - tfx, e1 = s1v[a] - tfy, e4 = o4 - 1.0f;
                l_l2 += (double)(e0*e0 + e1*e1 + d2*d2 + d3*d3 + e4*e4);
                int idx = atomicAdd(&sCnt, 1);
                sPos[idx] = (cell << 7) | sCls[k];
                o5[a][0]=s0[a]; o5[a][1]=s1v[a]; o5[a][2]=ow2; o5[a][3]=ow3; o5[a][4]=o4;
            } else {
                l_obj += (double)bce1(o4, 0.0f);
                l_l2  += (double)(o4*o4);
                o5[a][0]=0.0f; o5[a][1]=0.0f; o5[a][2]=0.0f; o5[a][3]=0.0f; o5[a][4]=o4;
            }
        }
    }
    __syncthreads();   /* all sU.part reads done -> union repurpose safe */

    if (pv){
        int slot = nbase + half - n0;
        #pragma unroll
        for (int a = 0; a < NA; a++){
            float* d5 = &sU.out5[a][slot][0];
            d5[0]=o5[a][0]; d5[1]=o5[a][1]; d5[2]=o5[a][2];
            d5[3]=o5[a][3]; d5[4]=o5[a][4];
        }
    }
    __syncthreads();

    /* ---- single-pass coalesced store of the 3 output regions ---- */
    #pragma unroll
    for (int a = 0; a < NA; a++){
        size_t e0 = 6 + ((size_t)((b*NA + a)*NPIX + n0))*NCH;
        float* base = dout + e0;
        int cnt = npb*NCH;
        int pad = (int)((4 - (e0 & 3)) & 3);
        if (pad > cnt) pad = cnt;
        if (tid < pad){
            int cell = tid/NCH, c = tid - cell*NCH;
            base[tid] = (c < 5) ? sU.out5[a][cell][c] : 0.0f;
        }
        int nv = (cnt - pad) >> 2;
        float4* b4 = (float4*)(base + pad);
        for (int j = tid; j < nv; j += TPB){
            int g = pad + (j << 2);
            float4 vv;
            { int cell = g/NCH,     c = g     - cell*NCH; vv.x = (c < 5) ? sU.out5[a][cell][c] : 0.0f; }
            { int cell = (g+1)/NCH, c = (g+1) - cell*NCH; vv.y = (c < 5) ? sU.out5[a][cell][c] : 0.0f; }
            { int cell = (g+2)/NCH, c = (g+2) - cell*NCH; vv.z = (c < 5) ? sU.out5[a][cell][c] : 0.0f; }
            { int cell = (g+3)/NCH, c = (g+3) - cell*NCH; vv.w = (c < 5) ? sU.out5[a][cell][c] : 0.0f; }
            b4[j] = vv;
        }
        int rem0 = pad + (nv << 2);
        if (rem0 + tid < cnt){
            int g = rem0 + tid;
            int cell = g/NCH, c = g - cell*NCH;
            base[g] = (c < 5) ? sU.out5[a][cell][c] : 0.0f;
        }
    }
    __syncthreads();

    /* ---- class pass for positives owned by this block ---- */
    {
        int lane = tid & 31, wid = tid >> 5;
        int cnt = sCnt;
        for (int q = 0; q < cnt; q++){
            int pk   = sPos[q];
            int cell = pk >> 7;
            int cls  = pk & 127;
            int a    = (cell / NPIX) % NA;
            int pix  = cell % NPIX;
            sX[tid]       = xin[((size_t)b*CIN + tid)*NPIX + pix];
            sX[tid + 128] = xin[((size_t)b*CIN + tid + 128)*NPIX + pix];
            __syncthreads();

            const float* wbase = cw + (size_t)(a*NCH + 5 + wid*20)*CIN;
            float s[20];
            #pragma unroll
            for (int i = 0; i < 20; i++) s[i] = 0.0f;
            #pragma unroll
            for (int j = 0; j < 8; j++){
                float x = sX[lane + 32*j];
                #pragma unroll
                for (int i = 0; i < 20; i++)
                    s[i] += wbase[(size_t)i*CIN + lane + 32*j] * x;
            }
            #pragma unroll
            for (int i = 0; i < 20; i++){
                #pragma unroll
                for (int off = 16; off; off >>= 1)
                    s[i] += __shfl_down_sync(0xffffffffu, s[i], off);
            }
            if (lane == 0){
                float* oc = dout + 6 + (size_t)cell*NCH;
                #pragma unroll
                for (int i = 0; i < 20; i++){
                    int c = wid*20 + i;
                    float raw = s[i] + cb[a*NCH + 5 + c];
                    float sg = sigf(raw);
                    float t = (c == cls) ? 1.0f : 0.0f;
                    l_cl += (double)bce1(sg, t);
                    float d = sg - t;
                    l_l2 += (double)(d*d);
                    oc[5 + c] = sg;
                }
            }
            __syncthreads();
        }
    }

    /* ---- block reduce 5 doubles -> atomicAdd ---- */
    int lane = tid & 31, wid = tid >> 5;
    #pragma unroll
    for (int off = 16; off; off >>= 1){
        l_xy  += __shfl_down_sync(0xffffffffu, l_xy,  off);
        l_wh  += __shfl_down_sync(0xffffffffu, l_wh,  off);
        l_obj += __shfl_down_sync(0xffffffffu, l_obj, off);
        l_cl  += __shfl_down_sync(0xffffffffu, l_cl,  off);
        l_l2  += __shfl_down_sync(0xffffffffu, l_l2,  off);
    }
    if (lane == 0){ red[0][wid]=l_xy; red[1][wid]=l_wh; red[2][wid]=l_obj; red[3][wid]=l_cl; red[4][wid]=l_l2; }
    __syncthreads();
    if (tid == 0){
        double a0=0,a1=0,a2=0,a3=0,a4=0;
        #pragma unroll
        for (int i = 0; i < 4; i++){ a0+=red[0][i]; a1+=red[1][i]; a2+=red[2][i]; a3+=red[3][i]; a4+=red[4][i]; }
        atomicAdd(&g_acc[0], a0);
        atomicAdd(&g_acc[1], a1);
        atomicAdd(&g_acc[2], a2);
        atomicAdd(&g_acc[3], a3);
        atomicAdd(&g_acc[4], a4);

        __threadfence();
        unsigned int t = atomicInc(&g_done, TOTB - 1);
        if (t == TOTB - 1){
            double xy = atomicAdd(&g_acc[0], 0.0);
            double wh = atomicAdd(&g_acc[1], 0.0);
            double ob = atomicAdd(&g_acc[2], 0.0);
            double cl = atomicAdd(&g_acc[3], 0.0);
            double l2 = atomicAdd(&g_acc[4], 0.0);
            dout[0] = (float)(xy + wh + ob + cl);
            dout[1] = (float)xy;
            dout[2] = (float)wh;
            dout[3] = (float)ob;
            dout[4] = (float)cl;
            dout[5] = (float)l2;
            g_acc[0]=0.0; g_acc[1]=0.0; g_acc[2]=0.0; g_acc[3]=0.0; g_acc[4]=0.0;
            __threadfence();
        }
    }
}

extern "C" void kernel_launch(void* const* d_in, const int* in_sizes, int n_in,
                              void* d_out, int out_size)
{
    const float* xin    = (const float*)d_in[0];
    const float* labels = (const float*)d_in[1];
    const float* cw     = (const float*)d_in[2];
    const float* cb     = (const float*)d_in[3];
    float* dout = (float*)d_out;

    dim3 g(NBLK, BB);   /* 46 x 16 = 736 blocks */
    k_main<<<g, TPB>>>(xin, labels, cw, cb, dout);
}

// round 12
// speedup vs baseline: 1.2626x; 1.0288x over previous
#include <cuda_runtime.h>

#define BB 16
#define CIN 256
#define FF 76
#define NPIX (FF*FF)          /* 5776 */
#define NA 3
#define NCH 85
#define KK 50
#define PXB 256               /* pixels per block */
#define TPB 128
#define NGRP 64               /* pair-groups per block: each owns 4 pixels */
#define NBLK ((NPIX + PXB - 1)/PXB)   /* 23 */
#define TOTB (NBLK*BB)                /* 368 */

typedef unsigned long long ull;

__device__ double       g_acc[5];
__device__ unsigned int g_done;

__constant__ float c_AW[9] = {1.25f,2.0f,4.125f,3.75f,7.75f,7.375f,14.5f,19.5f,46.625f};
__constant__ float c_AH[9] = {1.625f,3.75f,2.875f,7.625f,5.625f,14.875f,11.25f,24.75f,40.75f};
__constant__ float c_MW[3] = {1.25f,2.0f,4.125f};
__constant__ float c_MH[3] = {1.625f,3.75f,2.875f};

__device__ __forceinline__ float sigf(float x){ return 1.0f/(1.0f + expf(-x)); }

__device__ __forceinline__ float bce1(float p, float t){
    float pc = fminf(fmaxf(p, 1e-12f), 0.99999988f);
    return -(t*logf(pc) + (1.0f - t)*logf(1.0f - pc));
}

__device__ __forceinline__ void fma2(ull& acc, ull a, ull b){
    asm("fma.rn.f32x2 %0, %1, %2, %0;" : "+l"(acc) : "l"(a), "l"(b));
}
__device__ __forceinline__ float2 u2f2(ull v){
    float2 r; asm("mov.b64 {%0, %1}, %2;" : "=f"(r.x), "=f"(r.y) : "l"(v)); return r;
}

__global__ void __launch_bounds__(TPB, 3)
k_main(const float* __restrict__ xin, const float* __restrict__ labels,
       const float* __restrict__ cw,  const float* __restrict__ cb,
       float* __restrict__ dout)
{
    __shared__ __align__(16) ull sW2[15][CIN];   /* (w,w) pairs: 30.7 KB */
    __shared__ union {
        ull   part[2][15][NGRP][2];      /* conv partials per half (phase A): 30.7 KB */
        float out5[NA][PXB][5];          /* staged ch0-4 values    (phase B): 15.4 KB */
    } sU;
    __shared__ float  sB[15];
    __shared__ float  sTx[KK], sTy[KK], sTw[KK], sTh[KK];
    __shared__ float  sX1[KK], sY1[KK], sX2[KK], sY2[KK], sAr[KK];
    __shared__ int    sCls[KK];
    __shared__ int    sOwn[NA*PXB];
    __shared__ int    sPos[KK];
    __shared__ int    sCnt;
    __shared__ float  sX[CIN];
    __shared__ double red[5][4];

    int tid = threadIdx.x;
    int b   = blockIdx.y;
    int n0  = blockIdx.x*PXB;
    int npb = NPIX - n0; if (npb > PXB) npb = PXB;   /* 256 or 144, mult of 4 */

    for (int i = tid; i < NA*PXB; i += TPB) sOwn[i] = -1;
    if (tid == 0) sCnt = 0;

    /* weights as (w,w) pairs */
    for (int i = tid; i < 15*CIN; i += TPB){
        int j = i >> 8, c = i & 255;
        int a = j/5, ch = j%5;
        float w = cw[(a*NCH + ch)*CIN + c];
        float2 p = make_float2(w, w);
        sW2[j][c] = *reinterpret_cast<ull*>(&p);
    }
    if (tid < 15){ int a = tid/5, ch = tid%5; sB[tid] = cb[a*NCH + ch]; }
    if (tid >= 64 && tid < 64 + KK){
        int t = tid - 64;
        const float* L = labels + (b*KK + t)*5;
        float cls=L[0], xc=L[1], yc=L[2], w=L[3], h=L[4];
        bool valid = (cls + xc + yc + w + h) > 0.0f;
        float tx = xc*(float)FF, ty = yc*(float)FF;
        float tw = w *(float)FF, th = h *(float)FF;
        sTx[t]=tx; sTy[t]=ty; sTw[t]=tw; sTh[t]=th;
        sCls[t] = (int)cls;
        if (valid){
            sX1[t]=tx-tw*0.5f; sY1[t]=ty-th*0.5f;
            sX2[t]=tx+tw*0.5f; sY2[t]=ty+th*0.5f;
            sAr[t]=tw*th;
        } else {
            sX1[t]= 3.0e38f; sY1[t]= 3.0e38f;
            sX2[t]=-3.0e38f; sY2[t]=-3.0e38f;
            sAr[t]= 0.0f;
        }
        float ta = tw*th;
        float best = -1.0f; int bn = 0;
        #pragma unroll
        for (int a = 0; a < 9; a++){
            float inter = fminf(tw, c_AW[a]) * fminf(th, c_AH[a]);
            float iou = inter / (ta + c_AW[a]*c_AH[a] - inter);
            if (iou > best){ best = iou; bn = a; }
        }
        if (valid && bn < 3){
            int ii = (int)tx, jj = (int)ty;
            int slot = jj*FF + ii - n0;
            if (slot >= 0 && slot < PXB) atomicMax(&sOwn[bn*PXB + slot], t);
        }
    }
    __syncthreads();

    int pt   = tid & (NGRP-1);      /* group index: owns pixels 4pt..4pt+3 */
    int half = tid >> 6;            /* channel half */
    int nbase = n0 + 4*pt;
    bool pv = (4*pt < npb);
    int nb = pv ? nbase : n0;
    double l_xy=0.0, l_wh=0.0, l_obj=0.0, l_cl=0.0, l_l2=0.0;

    /* ---- 15-ch conv, TWO pixel-pairs per thread, channels split by half ----
       x: one LDG.128 per channel (covers 4 pixels); weights LDS feed 8 fma2 */
    ull accA[15], accB[15];
    #pragma unroll
    for (int j = 0; j < 15; j++){ accA[j] = 0ULL; accB[j] = 0ULL; }
    {
        const ulonglong2* xq = reinterpret_cast<const ulonglong2*>(
            xin + (size_t)b*CIN*NPIX + nb);
        const int ST2 = NPIX/4;
        const int c0 = half*128;
        ulonglong2 x0=xq[(size_t)(c0+0)*ST2], x1=xq[(size_t)(c0+1)*ST2];
        ulonglong2 x2=xq[(size_t)(c0+2)*ST2], x3=xq[(size_t)(c0+3)*ST2];
        #pragma unroll 2
        for (int c = 0; c < 128; c += 4){
            int cp = (c + 4 < 128) ? c0 + c + 4 : c0;
            ulonglong2 y0=xq[(size_t)(cp+0)*ST2], y1=xq[(size_t)(cp+1)*ST2];
            ulonglong2 y2=xq[(size_t)(cp+2)*ST2], y3=xq[(size_t)(cp+3)*ST2];
            int cc = c0 + c;
            #pragma unroll
            for (int j = 0; j < 15; j++){
                ulonglong2 wA = *reinterpret_cast<const ulonglong2*>(&sW2[j][cc]);
                ulonglong2 wB = *reinterpret_cast<const ulonglong2*>(&sW2[j][cc+2]);
                fma2(accA[j], wA.x, x0.x); fma2(accB[j], wA.x, x0.y);
                fma2(accA[j], wA.y, x1.x); fma2(accB[j], wA.y, x1.y);
                fma2(accA[j], wB.x, x2.x); fma2(accB[j], wB.x, x2.y);
                fma2(accA[j], wB.y, x3.x); fma2(accB[j], wB.y, x3.y);
            }
            x0=y0; x1=y1; x2=y2; x3=y3;
        }
    }
    #pragma unroll
    for (int j = 0; j < 15; j++){
        sU.part[half][j][pt][0] = accA[j];
        sU.part[half][j][pt][1] = accB[j];
    }
    __syncthreads();

    /* ---- each thread finalizes TWO pixels: nbase+half and nbase+2+half ---- */
    float o5[2][3][5];

    if (pv){
        float a2[2][15];   /* [px][j]: px0 = pair A lane half, px1 = pair B lane half */
        #pragma unroll
        for (int j = 0; j < 15; j++){
            float2 fA0 = u2f2(sU.part[0][j][pt][0]);
            float2 fA1 = u2f2(sU.part[1][j][pt][0]);
            float2 fB0 = u2f2(sU.part[0][j][pt][1]);
            float2 fB1 = u2f2(sU.part[1][j][pt][1]);
            a2[0][j] = half ? (fA0.y + fA1.y) : (fA0.x + fA1.x);
            a2[1][j] = half ? (fB0.y + fB1.y) : (fB0.x + fB1.x);
        }

        float s0[2][3], s1v[2][3], s4v[2][3], r2v[2][3], r3v[2][3];
        float bx1[2][3], by1[2][3], bx2[2][3], by2[2][3], bap[2][3];
        #pragma unroll
        for (int px = 0; px < 2; px++){
            int n = nbase + 2*px + half;
            int h = n / FF, w = n % FF;
            #pragma unroll
            for (int a = 0; a < NA; a++){
                float r0 = a2[px][a*5+0] + sB[a*5+0];
                float r1 = a2[px][a*5+1] + sB[a*5+1];
                float r2 = a2[px][a*5+2] + sB[a*5+2];
                float r3 = a2[px][a*5+3] + sB[a*5+3];
                float r4 = a2[px][a*5+4] + sB[a*5+4];
                s0[px][a]=sigf(r0); s1v[px][a]=sigf(r1); s4v[px][a]=sigf(r4);
                r2v[px][a]=r2; r3v[px][a]=r3;
                float pxc = s0[px][a] + (float)w, pyc = s1v[px][a] + (float)h;
                float pw = expf(r2)*c_MW[a], ph = expf(r3)*c_MH[a];
                bx1[px][a]=pxc-pw*0.5f; by1[px][a]=pyc-ph*0.5f;
                bx2[px][a]=pxc+pw*0.5f; by2[px][a]=pyc+ph*0.5f;
                bap[px][a]=pw*ph;
            }
        }

        bool ig[2][3] = {{false,false,false},{false,false,false}};
        #pragma unroll 2
        for (int k = 0; k < KK; k++){
            float lx1=sX1[k], ly1=sY1[k], lx2=sX2[k], ly2=sY2[k], ar=sAr[k];
            #pragma unroll
            for (int px = 0; px < 2; px++)
            #pragma unroll
            for (int a = 0; a < NA; a++){
                float dx = fminf(bx2[px][a], lx2) - fmaxf(bx1[px][a], lx1);
                float dy = fminf(by2[px][a], ly2) - fmaxf(by1[px][a], ly1);
                float inter = dx*dy;
                bool en = (dx > 0.0f) & (dy > 0.0f);
                ig[px][a] = ig[px][a] | (en & (inter > 0.7f*(bap[px][a] + ar - inter)));
            }
        }

        #pragma unroll
        for (int px = 0; px < 2; px++){
            int n = nbase + 2*px + half;
            #pragma unroll
            for (int a = 0; a < NA; a++){
                int cell = (b*NA + a)*NPIX + n;
                int k = sOwn[a*PXB + (n - n0)];
                bool m = (k >= 0);
                float obj = m ? 1.0f : (ig[px][a] ? 0.0f : 1.0f);
                float o4 = s4v[px][a] * obj;

                if (m){
                    float tx = sTx[k], ty = sTy[k], tw = sTw[k], th = sTh[k];
                    int ii = (int)tx, jj = (int)ty;
                    float tfx = tx - (float)ii, tfy = ty - (float)jj;
                    float lw = logf(tw / c_MW[a] + 1e-16f);
                    float lh = logf(th / c_MH[a] + 1e-16f);
                    float sc  = sqrtf(2.0f - tw*th/(float)NPIX);
                    float sc2 = sc*sc;
                    l_xy += (double)((bce1(s0[px][a], tfx) + bce1(s1v[px][a], tfy)) * sc2);
                    float ow2 = r2v[px][a]*sc, ow3 = r3v[px][a]*sc;
                    float tw2 = lw*sc, tw3 = lh*sc;
                    float d2 = ow2 - tw2, d3 = ow3 - tw3;
                    l_wh += 0.5*(double)(d2*d2 + d3*d3);
                    l_obj += (double)bce1(o4, 1.0f);
                    float e0 = s0[px][a] - tfx, e1 = s1v[px][a] - tfy, e4 = o4 - 1.0f;
                    l_l2 += (double)(e0*e0 + e1*e1 + d2*d2 + d3*d3 + e4*e4);
                    int idx = atomicAdd(&sCnt, 1);
                    sPos[idx] = (cell << 7) | sCls[k];
                    o5[px][a][0]=s0[px][a]; o5[px][a][1]=s1v[px][a];
                    o5[px][a][2]=ow2; o5[px][a][3]=ow3; o5[px][a][4]=o4;
                } else {
                    l_obj += (double)bce1(o4, 0.0f);
                    l_l2  += (double)(o4*o4);
                    o5[px][a][0]=0.0f; o5[px][a][1]=0.0f;
                    o5[px][a][2]=0.0f; o5[px][a][3]=0.0f; o5[px][a][4]=o4;
                }
            }
        }
    }
    __syncthreads();   /* all sU.part reads done -> union repurpose safe */

    if (pv){
        #pragma unroll
        for (int px = 0; px < 2; px++){
            int slot = nbase + 2*px + half - n0;
            #pragma unroll
            for (int a = 0; a < NA; a++){
                float* d5 = &sU.out5[a][slot][0];
                d5[0]=o5[px][a][0]; d5[1]=o5[px][a][1]; d5[2]=o5[px][a][2];
                d5[3]=o5[px][a][3]; d5[4]=o5[px][a][4];
            }
        }
    }
    __syncthreads();

    /* ---- single-pass coalesced store of the 3 output regions ---- */
    #pragma unroll
    for (int a = 0; a < NA; a++){
        size_t e0 = 6 + ((size_t)((b*NA + a)*NPIX + n0))*NCH;
        float* base = dout + e0;
        int cnt = npb*NCH;
        int pad = (int)((4 - (e0 & 3)) & 3);
        if (pad > cnt) pad = cnt;
        if (tid < pad){
            int cell = tid/NCH, c = tid - cell*NCH;
            base[tid] = (c < 5) ? sU.out5[a][cell][c] : 0.0f;
        }
        int nv = (cnt - pad) >> 2;
        float4* b4 = (float4*)(base + pad);
        for (int j = tid; j < nv; j += TPB){
            int g = pad + (j << 2);
            float4 vv;
            { int cell = g/NCH,     c = g     - cell*NCH; vv.x = (c < 5) ? sU.out5[a][cell][c] : 0.0f; }
            { int cell = (g+1)/NCH, c = (g+1) - cell*NCH; vv.y = (c < 5) ? sU.out5[a][cell][c] : 0.0f; }
            { int cell = (g+2)/NCH, c = (g+2) - cell*NCH; vv.z = (c < 5) ? sU.out5[a][cell][c] : 0.0f; }
            { int cell = (g+3)/NCH, c = (g+3) - cell*NCH; vv.w = (c < 5) ? sU.out5[a][cell][c] : 0.0f; }
            b4[j] = vv;
        }
        int rem0 = pad + (nv << 2);
        if (rem0 + tid < cnt){
            int g = rem0 + tid;
            int cell = g/NCH, c = g - cell*NCH;
            base[g] = (c < 5) ? sU.out5[a][cell][c] : 0.0f;
        }
    }
    __syncthreads();

    /* ---- class pass for positives owned by this block ---- */
    {
        int lane = tid & 31, wid = tid >> 5;
        int cnt = sCnt;
        for (int q = 0; q < cnt; q++){
            int pk   = sPos[q];
            int cell = pk >> 7;
            int cls  = pk & 127;
            int a    = (cell / NPIX) % NA;
            int pix  = cell % NPIX;
            sX[tid]       = xin[((size_t)b*CIN + tid)*NPIX + pix];
            sX[tid + 128] = xin[((size_t)b*CIN + tid + 128)*NPIX + pix];
            __syncthreads();

            const float* wbase = cw + (size_t)(a*NCH + 5 + wid*20)*CIN;
            float s[20];
            #pragma unroll
            for (int i = 0; i < 20; i++) s[i] = 0.0f;
            #pragma unroll
            for (int j = 0; j < 8; j++){
                float x = sX[lane + 32*j];
                #pragma unroll
                for (int i = 0; i < 20; i++)
                    s[i] += wbase[(size_t)i*CIN + lane + 32*j] * x;
            }
            #pragma unroll
            for (int i = 0; i < 20; i++){
                #pragma unroll
                for (int off = 16; off; off >>= 1)
                    s[i] += __shfl_down_sync(0xffffffffu, s[i], off);
            }
            if (lane == 0){
                float* oc = dout + 6 + (size_t)cell*NCH;
                #pragma unroll
                for (int i = 0; i < 20; i++){
                    int c = wid*20 + i;
                    float raw = s[i] + cb[a*NCH + 5 + c];
                    float sg = sigf(raw);
                    float t = (c == cls) ? 1.0f : 0.0f;
                    l_cl += (double)bce1(sg, t);
                    float d = sg - t;
                    l_l2 += (double)(d*d);
                    oc[5 + c] = sg;
                }
            }
            __syncthreads();
        }
    }

    /* ---- block reduce 5 doubles -> atomicAdd ---- */
    int lane = tid & 31, wid = tid >> 5;
    #pragma unroll
    for (int off = 16; off; off >>= 1){
        l_xy  += __shfl_down_sync(0xffffffffu, l_xy,  off);
        l_wh  += __shfl_down_sync(0xffffffffu, l_wh,  off);
        l_obj += __shfl_down_sync(0xffffffffu, l_obj, off);
        l_cl  += __shfl_down_sync(0xffffffffu, l_cl,  off);
        l_l2  += __shfl_down_sync(0xffffffffu, l_l2,  off);
    }
    if (lane == 0){ red[0][wid]=l_xy; red[1][wid]=l_wh; red[2][wid]=l_obj; red[3][wid]=l_cl; red[4][wid]=l_l2; }
    __syncthreads();
    if (tid == 0){
        double a0=0,a1=0,a2=0,a3=0,a4=0;
        #pragma unroll
        for (int i = 0; i < 4; i++){ a0+=red[0][i]; a1+=red[1][i]; a2+=red[2][i]; a3+=red[3][i]; a4+=red[4][i]; }
        atomicAdd(&g_acc[0], a0);
        atomicAdd(&g_acc[1], a1);
        atomicAdd(&g_acc[2], a2);
        atomicAdd(&g_acc[3], a3);
        atomicAdd(&g_acc[4], a4);

        __threadfence();
        unsigned int t = atomicInc(&g_done, TOTB - 1);
        if (t == TOTB - 1){
            double xy = atomicAdd(&g_acc[0], 0.0);
            double wh = atomicAdd(&g_acc[1], 0.0);
            double ob = atomicAdd(&g_acc[2], 0.0);
            double cl = atomicAdd(&g_acc[3], 0.0);
            double l2 = atomicAdd(&g_acc[4], 0.0);
            dout[0] = (float)(xy + wh + ob + cl);
            dout[1] = (float)xy;
            dout[2] = (float)wh;
            dout[3] = (float)ob;
            dout[4] = (float)cl;
            dout[5] = (float)l2;
            g_acc[0]=0.0; g_acc[1]=0.0; g_acc[2]=0.0; g_acc[3]=0.0; g_acc[4]=0.0;
            __threadfence();
        }
    }
}

extern "C" void kernel_launch(void* const* d_in, const int* in_sizes, int n_in,
                              void* d_out, int out_size)
{
    const float* xin    = (const float*)d_in[0];
    const float* labels = (const float*)d_in[1];
    const float* cw     = (const float*)d_in[2];
    const float* cb     = (const float*)d_in[3];
    float* dout = (float*)d_out;

    dim3 g(NBLK, BB);   /* 23 x 16 = 368 blocks */
    k_main<<<g, TPB>>>(xin, labels, cw, cb, dout);
}

// round 13
// speedup vs baseline: 1.3570x; 1.0747x over previous
#include <cuda_runtime.h>

#define BB 16
#define CIN 256
#define FF 76
#define NPIX (FF*FF)          /* 5776 */
#define NA 3
#define NCH 85
#define KK 50
#define PXB 160               /* pixels per block */
#define TPB 160               /* 5 warps */
#define NGRP 40               /* 4-pixel groups per block */
#define NBLK 37               /* ceil(5776/160) */
#define TOTB (NBLK*BB)        /* 592 = 148*4 exactly */
#define ST2 (NPIX/4)          /* 1444 ulonglong2 per channel */

typedef unsigned long long ull;

__device__ double       g_acc[5];
__device__ unsigned int g_done;

__constant__ float c_AW[9] = {1.25f,2.0f,4.125f,3.75f,7.75f,7.375f,14.5f,19.5f,46.625f};
__constant__ float c_AH[9] = {1.625f,3.75f,2.875f,7.625f,5.625f,14.875f,11.25f,24.75f,40.75f};
__constant__ float c_MW[3] = {1.25f,2.0f,4.125f};
__constant__ float c_MH[3] = {1.625f,3.75f,2.875f};

/* one union region, time-multiplexed: w2 (conv) -> part (combine) -> out5 (store) */
union UShared {
    ull   w2[15][CIN];            /* 30720 B */
    ull   part[4][15][NGRP][2];   /* 38400 B */
    float out5[NA][PXB][5];       /*  9600 B */
};
struct SMem {
    UShared u;
    float  sB[15];
    float  sTx[KK], sTy[KK], sTw[KK], sTh[KK];
    float  sX1[KK], sY1[KK], sX2[KK], sY2[KK], sAr[KK];
    int    sCls[KK];
    int    sOwn[NA*PXB];
    int    sPos[KK];
    int    sCnt;
    float  sX[CIN];
    double red[5][5];
};

__device__ __forceinline__ float sigf(float x){ return 1.0f/(1.0f + expf(-x)); }

__device__ __forceinline__ float bce1(float p, float t){
    float pc = fminf(fmaxf(p, 1e-12f), 0.99999988f);
    return -(t*logf(pc) + (1.0f - t)*logf(1.0f - pc));
}

__device__ __forceinline__ void fma2(ull& acc, ull a, ull b){
    asm("fma.rn.f32x2 %0, %1, %2, %0;" : "+l"(acc) : "l"(a), "l"(b));
}
__device__ __forceinline__ ull add2(ull a, ull b){
    ull r; asm("add.rn.f32x2 %0, %1, %2;" : "=l"(r) : "l"(a), "l"(b)); return r;
}
__device__ __forceinline__ float2 u2f2(ull v){
    float2 r; asm("mov.b64 {%0, %1}, %2;" : "=f"(r.x), "=f"(r.y) : "l"(v)); return r;
}

__global__ void __launch_bounds__(TPB, 4)
k_main(const float* __restrict__ xin, const float* __restrict__ labels,
       const float* __restrict__ cw,  const float* __restrict__ cb,
       float* __restrict__ dout)
{
    extern __shared__ __align__(16) char smraw[];
    SMem* sm = reinterpret_cast<SMem*>(smraw);

    int tid = threadIdx.x;
    int b   = blockIdx.y;
    int n0  = blockIdx.x*PXB;
    int npb = NPIX - n0; if (npb > PXB) npb = PXB;   /* 160 or 16, mult of 4 */

    for (int i = tid; i < NA*PXB; i += TPB) sm->sOwn[i] = -1;
    if (tid == 0) sm->sCnt = 0;

    /* weights as (w,w) pairs into union (phase: w2) */
    for (int i = tid; i < 15*CIN; i += TPB){
        int j = i >> 8, c = i & 255;
        int a = j/5, ch = j%5;
        float w = cw[(a*NCH + ch)*CIN + c];
        float2 p = make_float2(w, w);
        sm->u.w2[j][c] = *reinterpret_cast<ull*>(&p);
    }
    if (tid < 15){ int a = tid/5, ch = tid%5; sm->sB[tid] = cb[a*NCH + ch]; }
    if (tid >= 64 && tid < 64 + KK){
        int t = tid - 64;
        const float* L = labels + (b*KK + t)*5;
        float cls=L[0], xc=L[1], yc=L[2], w=L[3], h=L[4];
        bool valid = (cls + xc + yc + w + h) > 0.0f;
        float tx = xc*(float)FF, ty = yc*(float)FF;
        float tw = w *(float)FF, th = h *(float)FF;
        sm->sTx[t]=tx; sm->sTy[t]=ty; sm->sTw[t]=tw; sm->sTh[t]=th;
        sm->sCls[t] = (int)cls;
        if (valid){
            sm->sX1[t]=tx-tw*0.5f; sm->sY1[t]=ty-th*0.5f;
            sm->sX2[t]=tx+tw*0.5f; sm->sY2[t]=ty+th*0.5f;
            sm->sAr[t]=tw*th;
        } else {
            sm->sX1[t]= 3.0e38f; sm->sY1[t]= 3.0e38f;
            sm->sX2[t]=-3.0e38f; sm->sY2[t]=-3.0e38f;
            sm->sAr[t]= 0.0f;
        }
        float ta = tw*th;
        float best = -1.0f; int bn = 0;
        #pragma unroll
        for (int a = 0; a < 9; a++){
            float inter = fminf(tw, c_AW[a]) * fminf(th, c_AH[a]);
            float iou = inter / (ta + c_AW[a]*c_AH[a] - inter);
            if (iou > best){ best = iou; bn = a; }
        }
        if (valid && bn < 3){
            int ii = (int)tx, jj = (int)ty;
            int slot = jj*FF + ii - n0;
            if (slot >= 0 && slot < PXB) atomicMax(&sm->sOwn[bn*PXB + slot], t);
        }
    }
    __syncthreads();

    int q   = tid / NGRP;        /* channel quarter 0..3 (warp-quasi-uniform) */
    int grp = tid - q*NGRP;      /* 4-pixel group 0..39 */
    int nbase = n0 + 4*grp;
    bool pvc = (4*grp < npb);
    int nb = pvc ? nbase : n0;
    double l_xy=0.0, l_wh=0.0, l_obj=0.0, l_cl=0.0, l_l2=0.0;

    /* ---- conv: 4 pixels x 64 channels per thread, f32x2, full unroll ---- */
    ull accA[15], accB[15];
    #pragma unroll
    for (int j = 0; j < 15; j++){ accA[j] = 0ULL; accB[j] = 0ULL; }
    {
        const ulonglong2* xq = reinterpret_cast<const ulonglong2*>(
            xin + (size_t)b*CIN*NPIX + nb) + (size_t)(q*64)*ST2;
        const int wq = q*64;
        #pragma unroll
        for (int c = 0; c < 64; c += 4){
            ulonglong2 x0 = xq[(size_t)(c+0)*ST2];
            ulonglong2 x1 = xq[(size_t)(c+1)*ST2];
            ulonglong2 x2 = xq[(size_t)(c+2)*ST2];
            ulonglong2 x3 = xq[(size_t)(c+3)*ST2];
            #pragma unroll
            for (int j = 0; j < 15; j++){
                const ull* wp = &sm->u.w2[j][wq + c];
                ulonglong2 wA = *reinterpret_cast<const ulonglong2*>(wp);
                ulonglong2 wB = *reinterpret_cast<const ulonglong2*>(wp + 2);
                fma2(accA[j], wA.x, x0.x); fma2(accB[j], wA.x, x0.y);
                fma2(accA[j], wA.y, x1.x); fma2(accB[j], wA.y, x1.y);
                fma2(accA[j], wB.x, x2.x); fma2(accB[j], wB.x, x2.y);
                fma2(accA[j], wB.y, x3.x); fma2(accB[j], wB.y, x3.y);
            }
        }
    }
    __syncthreads();   /* all w2 reads done -> union becomes part */
    #pragma unroll
    for (int j = 0; j < 15; j++){
        sm->u.part[q][j][grp][0] = accA[j];
        sm->u.part[q][j][grp][1] = accB[j];
    }
    __syncthreads();

    /* ---- each thread finalizes ONE pixel: n0 + tid ---- */
    bool pvE = (tid < npb);
    float o5r[3][5];

    if (pvE){
        int slot = tid;
        int n = n0 + slot;
        int g2   = slot >> 2;
        int pair = (slot >> 1) & 1;
        int hf   = slot & 1;
        float a2[15];
        #pragma unroll
        for (int j = 0; j < 15; j++){
            ull s01 = add2(sm->u.part[0][j][g2][pair], sm->u.part[1][j][g2][pair]);
            ull s23 = add2(sm->u.part[2][j][g2][pair], sm->u.part[3][j][g2][pair]);
            float2 f = u2f2(add2(s01, s23));
            a2[j] = hf ? f.y : f.x;
        }

        int h = n / FF, w = n % FF;
        float s0[3], s1v[3], s4v[3], r2v[3], r3v[3];
        float bx1[3], by1[3], bx2[3], by2[3], bap[3];
        #pragma unroll
        for (int a = 0; a < NA; a++){
            float r0 = a2[a*5+0] + sm->sB[a*5+0];
            float r1 = a2[a*5+1] + sm->sB[a*5+1];
            float r2 = a2[a*5+2] + sm->sB[a*5+2];
            float r3 = a2[a*5+3] + sm->sB[a*5+3];
            float r4 = a2[a*5+4] + sm->sB[a*5+4];
            s0[a]=sigf(r0); s1v[a]=sigf(r1); s4v[a]=sigf(r4);
            r2v[a]=r2; r3v[a]=r3;
            float px = s0[a] + (float)w, py = s1v[a] + (float)h;
            float pw = expf(r2)*c_MW[a], ph = expf(r3)*c_MH[a];
            bx1[a]=px-pw*0.5f; by1[a]=py-ph*0.5f;
            bx2[a]=px+pw*0.5f; by2[a]=py+ph*0.5f;
            bap[a]=pw*ph;
        }

        bool ig[3] = {false,false,false};
        #pragma unroll 2
        for (int k = 0; k < KK; k++){
            float lx1=sm->sX1[k], ly1=sm->sY1[k];
            float lx2=sm->sX2[k], ly2=sm->sY2[k], ar=sm->sAr[k];
            #pragma unroll
            for (int a = 0; a < NA; a++){
                float dx = fminf(bx2[a], lx2) - fmaxf(bx1[a], lx1);
                float dy = fminf(by2[a], ly2) - fmaxf(by1[a], ly1);
                float inter = dx*dy;
                bool en = (dx > 0.0f) & (dy > 0.0f);
                ig[a] = ig[a] | (en & (inter > 0.7f*(bap[a] + ar - inter)));
            }
        }

        #pragma unroll
        for (int a = 0; a < NA; a++){
            int cell = (b*NA + a)*NPIX + n;
            int k = sm->sOwn[a*PXB + slot];
            bool m = (k >= 0);
            float obj = m ? 1.0f : (ig[a] ? 0.0f : 1.0f);
            float o4 = s4v[a] * obj;

            if (m){
                float tx = sm->sTx[k], ty = sm->sTy[k];
                float tw = sm->sTw[k], th = sm->sTh[k];
                int ii = (int)tx, jj = (int)ty;
                float tfx = tx - (float)ii, tfy = ty - (float)jj;
                float lw = logf(tw / c_MW[a] + 1e-16f);
                float lh = logf(th / c_MH[a] + 1e-16f);
                float sc  = sqrtf(2.0f - tw*th/(float)NPIX);
                float sc2 = sc*sc;
                l_xy += (double)((bce1(s0[a], tfx) + bce1(s1v[a], tfy)) * sc2);
                float ow2 = r2v[a]*sc, ow3 = r3v[a]*sc;
                float tw2 = lw*sc, tw3 = lh*sc;
                float d2 = ow2 - tw2, d3 = ow3 - tw3;
                l_wh += 0.5*(double)(d2*d2 + d3*d3);
                l_obj += (double)bce1(o4, 1.0f);
                float e0 = s0[a] - tfx, e1 = s1v[a] - tfy, e4 = o4 - 1.0f;
                l_l2 += (double)(e0*e0 + e1*e1 + d2*d2 + d3*d3 + e4*e4);
                int idx = atomicAdd(&sm->sCnt, 1);
                sm->sPos[idx] = (cell << 7) | sm->sCls[k];
                o5r[a][0]=s0[a]; o5r[a][1]=s1v[a]; o5r[a][2]=ow2; o5r[a][3]=ow3; o5r[a][4]=o4;
            } else {
                l_obj += (double)bce1(o4, 0.0f);
                l_l2  += (double)(o4*o4);
                o5r[a][0]=0.0f; o5r[a][1]=0.0f; o5r[a][2]=0.0f; o5r[a][3]=0.0f; o5r[a][4]=o4;
            }
        }
    }
    __syncthreads();   /* all part reads done -> union becomes out5 */

    if (pvE){
        #pragma unroll
        for (int a = 0; a < NA; a++){
            float* d5 = &sm->u.out5[a][tid][0];
            d5[0]=o5r[a][0]; d5[1]=o5r[a][1]; d5[2]=o5r[a][2];
            d5[3]=o5r[a][3]; d5[4]=o5r[a][4];
        }
    }
    __syncthreads();

    /* ---- single-pass coalesced store of the 3 output regions ---- */
    #pragma unroll
    for (int a = 0; a < NA; a++){
        size_t e0 = 6 + ((size_t)((b*NA + a)*NPIX + n0))*NCH;
        float* base = dout + e0;
        int cnt = npb*NCH;
        int pad = (int)((4 - (e0 & 3)) & 3);
        if (pad > cnt) pad = cnt;
        if (tid < pad){
            int cell = tid/NCH, c = tid - cell*NCH;
            base[tid] = (c < 5) ? sm->u.out5[a][cell][c] : 0.0f;
        }
        int nv = (cnt - pad) >> 2;
        float4* b4 = (float4*)(base + pad);
        for (int j = tid; j < nv; j += TPB){
            int g = pad + (j << 2);
            float4 vv;
            { int cell = g/NCH,     c = g     - cell*NCH; vv.x = (c < 5) ? sm->u.out5[a][cell][c] : 0.0f; }
            { int cell = (g+1)/NCH, c = (g+1) - cell*NCH; vv.y = (c < 5) ? sm->u.out5[a][cell][c] : 0.0f; }
            { int cell = (g+2)/NCH, c = (g+2) - cell*NCH; vv.z = (c < 5) ? sm->u.out5[a][cell][c] : 0.0f; }
            { int cell = (g+3)/NCH, c = (g+3) - cell*NCH; vv.w = (c < 5) ? sm->u.out5[a][cell][c] : 0.0f; }
            b4[j] = vv;
        }
        int rem0 = pad + (nv << 2);
        if (rem0 + tid < cnt){
            int g = rem0 + tid;
            int cell = g/NCH, c = g - cell*NCH;
            base[g] = (c < 5) ? sm->u.out5[a][cell][c] : 0.0f;
        }
    }
    __syncthreads();

    /* ---- class pass: 5 warps x 16 classes per positive ---- */
    {
        int lane = tid & 31, wid = tid >> 5;   /* wid 0..4 */
        int cnt = sm->sCnt;
        for (int qd = 0; qd < cnt; qd++){
            int pk   = sm->sPos[qd];
            int cell = pk >> 7;
            int cls  = pk & 127;
            int a    = (cell / NPIX) % NA;
            int pix  = cell % NPIX;
            for (int i = tid; i < CIN; i += TPB)
                sm->sX[i] = xin[((size_t)b*CIN + i)*NPIX + pix];
            __syncthreads();

            const float* wbase = cw + (size_t)(a*NCH + 5 + wid*16)*CIN;
            float s[16];
            #pragma unroll
            for (int i = 0; i < 16; i++) s[i] = 0.0f;
            #pragma unroll
            for (int j = 0; j < 8; j++){
                float x = sm->sX[lane + 32*j];
                #pragma unroll
                for (int i = 0; i < 16; i++)
                    s[i] += wbase[(size_t)i*CIN + lane + 32*j] * x;
            }
            #pragma unroll
            for (int i = 0; i < 16; i++){
                #pragma unroll
                for (int off = 16; off; off >>= 1)
                    s[i] += __shfl_down_sync(0xffffffffu, s[i], off);
            }
            if (lane == 0){
                float* oc = dout + 6 + (size_t)cell*NCH;
                #pragma unroll
                for (int i = 0; i < 16; i++){
                    int c = wid*16 + i;
                    float raw = s[i] + cb[a*NCH + 5 + c];
                    float sg = sigf(raw);
                    float t = (c == cls) ? 1.0f : 0.0f;
                    l_cl += (double)bce1(sg, t);
                    float d = sg - t;
                    l_l2 += (double)(d*d);
                    oc[5 + c] = sg;
                }
            }
            __syncthreads();
        }
    }

    /* ---- block reduce 5 doubles -> atomicAdd ---- */
    int lane = tid & 31, wid = tid >> 5;
    #pragma unroll
    for (int off = 16; off; off >>= 1){
        l_xy  += __shfl_down_sync(0xffffffffu, l_xy,  off);
        l_wh  += __shfl_down_sync(0xffffffffu, l_wh,  off);
        l_obj += __shfl_down_sync(0xffffffffu, l_obj, off);
        l_cl  += __shfl_down_sync(0xffffffffu, l_cl,  off);
        l_l2  += __shfl_down_sync(0xffffffffu, l_l2,  off);
    }
    if (lane == 0){
        sm->red[0][wid]=l_xy; sm->red[1][wid]=l_wh; sm->red[2][wid]=l_obj;
        sm->red[3][wid]=l_cl; sm->red[4][wid]=l_l2;
    }
    __syncthreads();
    if (tid == 0){
        double a0=0,a1=0,a2s=0,a3=0,a4=0;
        #pragma unroll
        for (int i = 0; i < 5; i++){
            a0+=sm->red[0][i]; a1+=sm->red[1][i]; a2s+=sm->red[2][i];
            a3+=sm->red[3][i]; a4+=sm->red[4][i];
        }
        atomicAdd(&g_acc[0], a0);
        atomicAdd(&g_acc[1], a1);
        atomicAdd(&g_acc[2], a2s);
        atomicAdd(&g_acc[3], a3);
        atomicAdd(&g_acc[4], a4);

        __threadfence();
        unsigned int t = atomicInc(&g_done, TOTB - 1);
        if (t == TOTB - 1){
            double xy = atomicAdd(&g_acc[0], 0.0);
            double wh = atomicAdd(&g_acc[1], 0.0);
            double ob = atomicAdd(&g_acc[2], 0.0);
            double cl = atomicAdd(&g_acc[3], 0.0);
            double l2 = atomicAdd(&g_acc[4], 0.0);
            dout[0] = (float)(xy + wh + ob + cl);
            dout[1] = (float)xy;
            dout[2] = (float)wh;
            dout[3] = (float)ob;
            dout[4] = (float)cl;
            dout[5] = (float)l2;
            g_acc[0]=0.0; g_acc[1]=0.0; g_acc[2]=0.0; g_acc[3]=0.0; g_acc[4]=0.0;
            __threadfence();
        }
    }
}

extern "C" void kernel_launch(void* const* d_in, const int* in_sizes, int n_in,
                              void* d_out, int out_size)
{
    const float* xin    = (const float*)d_in[0];
    const float* labels = (const float*)d_in[1];
    const float* cw     = (const float*)d_in[2];
    const float* cb     = (const float*)d_in[3];
    float* dout = (float*)d_out;

    static int smem_set = 0;
    int smem = (int)sizeof(SMem);
    if (!smem_set){
        cudaFuncSetAttribute(k_main, cudaFuncAttributeMaxDynamicSharedMemorySize, smem);
        smem_set = 1;
    }
    dim3 g(NBLK, BB);   /* 37 x 16 = 592 blocks = exactly 4.0/SM */
    k_main<<<g, TPB, smem>>>(xin, labels, cw, cb, dout);
}